// round 7
// baseline (speedup 1.0000x reference)
#include <cuda_runtime.h>
#include <math.h>

#define NPTS     4096
#define NB       16
#define NCLOUD   32
#define NBINS    128
#define SORT_TPB 256
#define MAIN_TPB 1024
#define MAIN_GRID 128

__device__ float g_sx[NCLOUD][NPTS];
__device__ float g_sy[NCLOUD][NPTS];
__device__ float g_sz[NCLOUD][NPTS];
__device__ float g_su[NCLOUD][NPTS];
__device__ int   g_binstart[NCLOUD][NBINS + 1];
__device__ float g_zmin[NCLOUD];
__device__ float g_binw[NCLOUD];
__device__ float g_accum;       // zero at entry/exit of every launch
__device__ unsigned g_count;    // zero at entry/exit of every launch

typedef unsigned long long u64;

static __device__ __forceinline__ u64 bcast2(float v) {
    u64 r;
    asm("mov.b64 %0, {%1, %1};" : "=l"(r) : "f"(v));
    return r;
}
static __device__ __forceinline__ void unpack2(u64 v, float &lo, float &hi) {
    asm("mov.b64 {%0, %1}, %2;" : "=f"(lo), "=f"(hi) : "l"(v));
}
static __device__ __forceinline__ u64 fma2(u64 a, u64 b, u64 c) {
    u64 d;
    asm("fma.rn.f32x2 %0, %1, %2, %3;" : "=l"(d) : "l"(a), "l"(b), "l"(c));
    return d;
}

// ---------------- sort kernel: bucket each cloud by z into NBINS bins -------
__global__ void __launch_bounds__(SORT_TPB) sort_kernel(const float* __restrict__ tpl,
                                                        const float* __restrict__ src) {
    const int c = blockIdx.x;   // 0..15 = template batches, 16..31 = source
    const float* P = (c < NB) ? (tpl + (size_t)c * NPTS * 3)
                              : (src + (size_t)(c - NB) * NPTS * 3);
    __shared__ float rmin[SORT_TPB / 32], rmax[SORT_TPB / 32];
    __shared__ int hist[NBINS];
    __shared__ int boff[NBINS + 1];
    __shared__ float s_zmin, s_inv;

    const int tid = threadIdx.x;
    float mn = 3.4e38f, mx = -3.4e38f;
    for (int p = tid; p < NPTS; p += SORT_TPB) {
        float z = P[3 * p + 2];
        mn = fminf(mn, z);
        mx = fmaxf(mx, z);
    }
#pragma unroll
    for (int o = 16; o; o >>= 1) {
        mn = fminf(mn, __shfl_xor_sync(0xffffffffu, mn, o));
        mx = fmaxf(mx, __shfl_xor_sync(0xffffffffu, mx, o));
    }
    if ((tid & 31) == 0) { rmin[tid >> 5] = mn; rmax[tid >> 5] = mx; }
    if (tid < NBINS) hist[tid] = 0;
    __syncthreads();
    if (tid == 0) {
        float zmin = rmin[0], zmax = rmax[0];
        for (int w = 1; w < SORT_TPB / 32; w++) {
            zmin = fminf(zmin, rmin[w]);
            zmax = fmaxf(zmax, rmax[w]);
        }
        float binw = fmaxf((zmax - zmin) / NBINS, 1e-30f);
        s_zmin = zmin;
        s_inv = 1.0f / binw;
        g_zmin[c] = zmin;
        g_binw[c] = binw;
    }
    __syncthreads();
    const float zmin = s_zmin, inv = s_inv;

    for (int p = tid; p < NPTS; p += SORT_TPB) {
        float z = P[3 * p + 2];
        int bn = min(max((int)((z - zmin) * inv), 0), NBINS - 1);
        atomicAdd(&hist[bn], 1);
    }
    __syncthreads();
    if (tid == 0) {
        int acc = 0;
        for (int k = 0; k < NBINS; k++) { boff[k] = acc; acc += hist[k]; }
        boff[NBINS] = acc;   // == NPTS
    }
    __syncthreads();
    if (tid < NBINS) hist[tid] = 0;
    __syncthreads();
    for (int p = tid; p < NPTS; p += SORT_TPB) {
        float x = P[3 * p + 0], y = P[3 * p + 1], z = P[3 * p + 2];
        int bn = min(max((int)((z - zmin) * inv), 0), NBINS - 1);
        int idx = boff[bn] + atomicAdd(&hist[bn], 1);
        g_sx[c][idx] = x;
        g_sy[c][idx] = y;
        g_sz[c][idx] = z;
        g_su[c][idx] = x * x + y * y + z * z;
    }
    for (int k = tid; k <= NBINS; k += SORT_TPB) g_binstart[c][k] = boff[k];
}

// ---------------- main kernel: windowed NN scan over sorted bins ------------
// block b: cloud-pair cp = b>>2 (dir = cp>>4, batch = cp&15); 4 blocks/pair.
// warp = 32 consecutive sorted queries; expand z-window while
// z_gap^2 <= warp_max(qu + curmin)  (curmin tracks dist^2 - |q|^2).
__global__ void __launch_bounds__(MAIN_TPB) chamfer_main(float* __restrict__ out) {
    extern __shared__ float sm[];
    float* sx = sm;
    float* sy = sm + NPTS;
    float* sz = sm + 2 * NPTS;
    float* su = sm + 3 * NPTS;
    int* sbin = (int*)(sm + 4 * NPTS);   // NBINS+1 ints

    const int tid = threadIdx.x;
    const int b = blockIdx.x;
    const int cp = b >> 2;
    const int dir = cp >> 4;
    const int batch = cp & 15;
    const int qcl = (dir == 0) ? batch : NB + batch;   // query cloud
    const int dcl = (dir == 0) ? NB + batch : batch;   // database cloud

    for (int p = tid; p < NPTS; p += MAIN_TPB) {
        sx[p] = g_sx[dcl][p];
        sy[p] = g_sy[dcl][p];
        sz[p] = g_sz[dcl][p];
        su[p] = g_su[dcl][p];
    }
    for (int k = tid; k <= NBINS; k += MAIN_TPB) sbin[k] = g_binstart[dcl][k];
    __syncthreads();

    const float zmin = g_zmin[dcl];
    const float binw = g_binw[dcl];
    const float invw = 1.0f / binw;

    const int warp = tid >> 5, lane = tid & 31;
    const int q = (((b & 3) * 32 + warp) << 5) + lane;  // sorted query index

    const float qx = g_sx[qcl][q], qy = g_sy[qcl][q], qz = g_sz[qcl][q];
    const float qu = g_su[qcl][q];
    const u64 pqx = bcast2(-2.0f * qx);
    const u64 pqy = bcast2(-2.0f * qy);
    const u64 pqz = bcast2(-2.0f * qz);

    float wlo = qz, whi = qz;
#pragma unroll
    for (int o = 16; o; o >>= 1) {
        wlo = fminf(wlo, __shfl_xor_sync(0xffffffffu, wlo, o));
        whi = fmaxf(whi, __shfl_xor_sync(0xffffffffu, whi, o));
    }
    int lo = min(max((int)((wlo - zmin) * invw), 0), NBINS - 1);
    int hi = min(max((int)((whi - zmin) * invw), 0), NBINS - 1);

    float bA = 3.4e38f, bB = 3.4e38f;
    const ulonglong2* vx = (const ulonglong2*)sx;
    const ulonglong2* vy = (const ulonglong2*)sy;
    const ulonglong2* vz = (const ulonglong2*)sz;
    const ulonglong2* vu = (const ulonglong2*)su;

    auto scan = [&](int a, int e) {
        int j1 = (e + 3) >> 2;
        for (int j = a >> 2; j < j1; j++) {
            ulonglong2 bx = vx[j], by = vy[j], bz = vz[j], bu = vu[j];
            u64 a01 = fma2(pqz, bz.x, bu.x);
            a01 = fma2(pqy, by.x, a01);
            a01 = fma2(pqx, bx.x, a01);
            u64 a23 = fma2(pqz, bz.y, bu.y);
            a23 = fma2(pqy, by.y, a23);
            a23 = fma2(pqx, bx.y, a23);
            float l0, h0, l1, h1;
            unpack2(a01, l0, h0);
            unpack2(a23, l1, h1);
            bA = fminf(bA, fminf(l0, l1));
            bB = fminf(bB, fminf(h0, h1));
        }
    };

    // initial window: all bins spanned by the warp's queries
    scan(sbin[lo], sbin[hi + 1]);

    // expand outward while the z-gap cannot rule out an improvement.
    // true best dist^2 for a lane = qu + min(bA,bB); prune radius is the warp
    // max of that (clamped at 0).
    while (true) {
        float m = qu + fminf(bA, bB);
#pragma unroll
        for (int o = 16; o; o >>= 1) m = fmaxf(m, __shfl_xor_sync(0xffffffffu, m, o));
        m = fmaxf(m, 0.0f);
        bool cl = lo > 0, cr = hi < NBINS - 1;
        float dl = cl ? (wlo - (zmin + (float)lo * binw)) : 0.0f;
        float dr = cr ? ((zmin + (float)(hi + 1) * binw) - whi) : 0.0f;
        bool okL = cl && dl * dl <= m;
        bool okR = cr && dr * dr <= m;
        if (!okL && !okR) break;
        if (okL && (!okR || dl <= dr)) {
            lo--;
            scan(sbin[lo], sbin[lo + 1]);
        } else {
            hi++;
            scan(sbin[hi], sbin[hi + 1]);
        }
    }

    float s = sqrtf(fmaxf(qu + fminf(bA, bB), 0.0f));

    // block reduction
#pragma unroll
    for (int o = 16; o; o >>= 1) s += __shfl_xor_sync(0xffffffffu, s, o);
    __syncthreads();                      // all warps done reading sm
    if (lane == 0) sm[warp] = s;
    __syncthreads();
    if (tid == 0) {
        float t = 0.0f;
#pragma unroll
        for (int w = 0; w < MAIN_TPB / 32; w++) t += sm[w];
        atomicAdd(&g_accum, t);
        __threadfence();
        unsigned old = atomicAdd(&g_count, 1u);
        if (old == MAIN_GRID - 1) {
            __threadfence();
            float total = atomicAdd(&g_accum, 0.0f);
            out[0] = total * (1.0f / 131072.0f);   // / (2*16*4096)
            g_accum = 0.0f;
            __threadfence();
            atomicExch(&g_count, 0u);
        }
    }
}

extern "C" void kernel_launch(void* const* d_in, const int* in_sizes, int n_in,
                              void* d_out, int out_size) {
    const float* tpl = (const float*)d_in[0];
    const float* src = (const float*)d_in[1];
    (void)in_sizes; (void)n_in; (void)out_size;

    const int smem = 4 * NPTS * (int)sizeof(float) + (NBINS + 1) * (int)sizeof(int);
    cudaFuncSetAttribute(chamfer_main, cudaFuncAttributeMaxDynamicSharedMemorySize, smem);

    sort_kernel<<<NCLOUD, SORT_TPB>>>(tpl, src);
    chamfer_main<<<MAIN_GRID, MAIN_TPB, smem>>>((float*)d_out);
}